// round 10
// baseline (speedup 1.0000x reference)
#include <cuda_runtime.h>
#include <cuda_bf16.h>

#define N_GROUPS 256
#define EMBED 1024
#define VEC4 (EMBED / 4)     // 256 float4 per row
#define KSPLIT 16
#define KPB (EMBED / KSPLIT) // 64 k-values per gemm block
#define NPART (N_GROUPS * N_GROUPS)   // 65536
#define LOSS_BLOCKS 128

// Scratch (device globals; no allocation allowed)
__device__ float g_im_mean[N_GROUPS * EMBED];
__device__ float g_s_mean[N_GROUPS * EMBED];
__device__ float g_Spart[KSPLIT * NPART];            // 4 MB
__device__ float g_diagpart[KSPLIT][N_GROUPS];       // compact diag partials
__device__ float g_loss_part[LOSS_BLOCKS];
__device__ int   g_count;   // zero at load; reset by last block each launch

// ---------------------------------------------------------------------------
// Kernel 1: segment mean. Grid = 2048 blocks of 64 threads.
//   blockIdx.x = g*8 + src*4 + quarter. Thread owns one float4 column of its
//   quarter-row. Software-pipelined 4+4 batches keep ~8 LDG.128 in flight.
//   (group sizes are >= 8 by construction: 8 + (i % 17))
// ---------------------------------------------------------------------------
__global__ void __launch_bounds__(64) segmean_kernel(
    const float* __restrict__ im, const float* __restrict__ s,
    const int* __restrict__ num_clips, const int* __restrict__ num_caps)
{
    const int b = blockIdx.x;
    const int g = b >> 3;
    const bool is_im = ((b >> 2) & 1) == 0;
    const int quarter = b & 3;
    const int* __restrict__ cnt = is_im ? num_clips : num_caps;
    const float4* __restrict__ src = (const float4*)(is_im ? im : s);
    float4* __restrict__ dst = (float4*)(is_im ? g_im_mean : g_s_mean);

    const int t = threadIdx.x;

    // start = sum of counts with index < g (4 counts/thread, 2-warp reduce)
    int contrib = 0;
    #pragma unroll
    for (int u = 0; u < 4; u++) {
        int k = t + u * 64;
        int c = cnt[k];
        contrib += (k < g) ? c : 0;
    }
    #pragma unroll
    for (int o = 16; o; o >>= 1) contrib += __shfl_xor_sync(0xFFFFFFFFu, contrib, o);
    __shared__ int ws[2];
    if ((t & 31) == 0) ws[t >> 5] = contrib;
    __syncthreads();
    const int start = ws[0] + ws[1];
    const int n = cnt[g];
    const float inv = 1.0f / (float)n;

    const float4* p = src + (size_t)start * VEC4 + quarter * 64 + t;

    float ax = 0.f, ay = 0.f, az = 0.f, aw = 0.f;

    // preload batch of 4 (n >= 8 guaranteed)
    float4 x0 = p[0];
    float4 x1 = p[VEC4];
    float4 x2 = p[2 * (size_t)VEC4];
    float4 x3 = p[3 * (size_t)VEC4];
    int r = 4;
    for (; r + 4 <= n; r += 4) {
        float4 y0 = p[(size_t)(r + 0) * VEC4];
        float4 y1 = p[(size_t)(r + 1) * VEC4];
        float4 y2 = p[(size_t)(r + 2) * VEC4];
        float4 y3 = p[(size_t)(r + 3) * VEC4];
        ax += (x0.x + x1.x) + (x2.x + x3.x);
        ay += (x0.y + x1.y) + (x2.y + x3.y);
        az += (x0.z + x1.z) + (x2.z + x3.z);
        aw += (x0.w + x1.w) + (x2.w + x3.w);
        x0 = y0; x1 = y1; x2 = y2; x3 = y3;
    }
    ax += (x0.x + x1.x) + (x2.x + x3.x);
    ay += (x0.y + x1.y) + (x2.y + x3.y);
    az += (x0.z + x1.z) + (x2.z + x3.z);
    aw += (x0.w + x1.w) + (x2.w + x3.w);
    for (; r < n; r++) {
        float4 x = p[(size_t)r * VEC4];
        ax += x.x; ay += x.y; az += x.z; aw += x.w;
    }

    float4 o4;
    o4.x = ax * inv; o4.y = ay * inv; o4.z = az * inv; o4.w = aw * inv;
    dst[(size_t)g * VEC4 + quarter * 64 + t] = o4;
}

// ---------------------------------------------------------------------------
// Kernel 2: K-split GEMM partials. Grid (4,4,16) = 256 blocks (ALL resident:
// 2 blocks/SM), 256 threads. 64x64 tile, K=64 per block loaded once into
// smem (k-major, pad 68) -> single __syncthreads -> uninterrupted FFMA loop.
// Diagonal tiles also write compact per-split diag partials.
// ---------------------------------------------------------------------------
__global__ void __launch_bounds__(256) gemm_partial_kernel()
{
    __shared__ float As[KPB][68];
    __shared__ float Bs[KPB][68];

    const int tid = threadIdx.x;
    const int tx = tid & 15;
    const int ty = tid >> 4;
    const int bi = blockIdx.y * 64;
    const int bj = blockIdx.x * 64;
    const int z  = blockIdx.z;
    const int kbase = z * KPB;

    const int lr = tid >> 2;   // 0..63 : tile row to load
    const int lc = tid & 3;    // 0..3  : k-quad within a 16-float stripe

    const float* Ab = &g_im_mean[(size_t)(bi + lr) * EMBED + kbase];
    const float* Bb = &g_s_mean [(size_t)(bj + lr) * EMBED + kbase];

    #pragma unroll
    for (int u = 0; u < 4; u++) {
        const int k = lc * 4 + u * 16;
        float4 a  = *(const float4*)(Ab + k);
        float4 bv = *(const float4*)(Bb + k);
        As[k + 0][lr] = a.x;  As[k + 1][lr] = a.y;
        As[k + 2][lr] = a.z;  As[k + 3][lr] = a.w;
        Bs[k + 0][lr] = bv.x; Bs[k + 1][lr] = bv.y;
        Bs[k + 2][lr] = bv.z; Bs[k + 3][lr] = bv.w;
    }
    __syncthreads();

    float acc[4][4] = {};
    #pragma unroll 16
    for (int kk = 0; kk < KPB; kk++) {
        float4 av = *(const float4*)&As[kk][ty * 4];
        float4 bw = *(const float4*)&Bs[kk][tx * 4];
        acc[0][0] += av.x * bw.x; acc[0][1] += av.x * bw.y;
        acc[0][2] += av.x * bw.z; acc[0][3] += av.x * bw.w;
        acc[1][0] += av.y * bw.x; acc[1][1] += av.y * bw.y;
        acc[1][2] += av.y * bw.z; acc[1][3] += av.y * bw.w;
        acc[2][0] += av.z * bw.x; acc[2][1] += av.z * bw.y;
        acc[2][2] += av.z * bw.z; acc[2][3] += av.z * bw.w;
        acc[3][0] += av.w * bw.x; acc[3][1] += av.w * bw.y;
        acc[3][2] += av.w * bw.z; acc[3][3] += av.w * bw.w;
    }

    float* outp = g_Spart + (size_t)z * NPART;
    #pragma unroll
    for (int i = 0; i < 4; i++) {
        float4 v;
        v.x = acc[i][0]; v.y = acc[i][1]; v.z = acc[i][2]; v.w = acc[i][3];
        *(float4*)&outp[(size_t)(bi + ty * 4 + i) * N_GROUPS + bj + tx * 4] = v;
    }

    // compact diagonal partials (diag tiles only; row==col => ty==tx, i==c)
    if (blockIdx.x == blockIdx.y && tx == ty) {
        #pragma unroll
        for (int i = 0; i < 4; i++)
            g_diagpart[z][bi + ty * 4 + i] = acc[i][i];
    }
}

// ---------------------------------------------------------------------------
// Kernel 3: fused K-split reduce + diag + hinge loss.
// 128 blocks x 128 threads; compact diag; last-block-arrival final sum.
// ---------------------------------------------------------------------------
__global__ void __launch_bounds__(128) fused_loss_kernel(float* __restrict__ out)
{
    __shared__ float diag_s[N_GROUPS];
    __shared__ float red[4];
    __shared__ int is_last;

    const int t = threadIdx.x;
    const int b = blockIdx.x;

    #pragma unroll
    for (int u = 0; u < 2; u++) {
        const int idx = t + u * 128;
        float d = 0.f;
        #pragma unroll
        for (int z = 0; z < KSPLIT; z++)
            d += g_diagpart[z][idx];
        diag_s[idx] = d;
    }
    __syncthreads();

    const int q = b * 128 + t;          // 0..16383
    float4 v = make_float4(0.f, 0.f, 0.f, 0.f);
    #pragma unroll
    for (int z = 0; z < KSPLIT; z++) {
        float4 p = *(const float4*)&g_Spart[(size_t)z * NPART + q * 4];
        v.x += p.x; v.y += p.y; v.z += p.z; v.w += p.w;
    }

    const int i = q >> 6;
    const int j0 = (q & 63) * 4;
    const float di = diag_s[i];
    float vv[4] = {v.x, v.y, v.z, v.w};
    float sum = 0.f;
    #pragma unroll
    for (int c = 0; c < 4; c++) {
        const int j = j0 + c;
        if (j != i)
            sum += fmaxf(vv[c] - di, 0.f) + fmaxf(vv[c] - diag_s[j], 0.f);
    }

    #pragma unroll
    for (int o = 16; o; o >>= 1) sum += __shfl_xor_sync(0xFFFFFFFFu, sum, o);
    if ((t & 31) == 0) red[t >> 5] = sum;
    __syncthreads();

    if (t == 0) {
        g_loss_part[b] = red[0] + red[1] + red[2] + red[3];
        __threadfence();
        int old = atomicAdd(&g_count, 1);
        is_last = (old == LOSS_BLOCKS - 1) ? 1 : 0;
    }
    __syncthreads();

    if (is_last) {
        float v2 = __ldcg(&g_loss_part[t]);
        #pragma unroll
        for (int o = 16; o; o >>= 1) v2 += __shfl_xor_sync(0xFFFFFFFFu, v2, o);
        if ((t & 31) == 0) red[t >> 5] = v2;
        __syncthreads();
        if (t == 0) {
            out[0] = red[0] + red[1] + red[2] + red[3];
            g_count = 0;                 // reset for next replay
        }
    }
}

extern "C" void kernel_launch(void* const* d_in, const int* in_sizes, int n_in,
                              void* d_out, int out_size)
{
    const float* im        = (const float*)d_in[0];
    const float* s         = (const float*)d_in[1];
    const int*   num_clips = (const int*)d_in[2];
    const int*   num_caps  = (const int*)d_in[3];
    float* out = (float*)d_out;

    segmean_kernel<<<2048, 64>>>(im, s, num_clips, num_caps);
    gemm_partial_kernel<<<dim3(4, 4, KSPLIT), 256>>>();
    fused_loss_kernel<<<LOSS_BLOCKS, 128>>>(out);
}

// round 11
// speedup vs baseline: 1.4413x; 1.4413x over previous
#include <cuda_runtime.h>
#include <cuda_bf16.h>

#define N_GROUPS 256
#define EMBED 1024
#define VEC4 (EMBED / 4)   // 256 float4 per row
#define KSPLIT 8
#define NPART (N_GROUPS * N_GROUPS)   // 65536
#define LOSS_BLOCKS 128

// Scratch (device globals; no allocation allowed)
__device__ float g_im_mean[N_GROUPS * EMBED];
__device__ float g_s_mean[N_GROUPS * EMBED];
__device__ float g_Spart[KSPLIT * NPART];          // 2 MB
__device__ float g_diagpart[KSPLIT][N_GROUPS];     // compact diag partials
__device__ float g_loss_part[LOSS_BLOCKS];
__device__ int   g_count;   // zero at load; reset by last block each launch

// ---------------------------------------------------------------------------
// Kernel 1: segment mean. Grid = 2048 blocks of 64 threads. (R7 proven)
//   blockIdx.x = g*8 + src*4 + quarter. Thread owns one float4 column of its
//   quarter-row; 8-deep register-batched LDG.128.
// ---------------------------------------------------------------------------
__global__ void __launch_bounds__(64) segmean_kernel(
    const float* __restrict__ im, const float* __restrict__ s,
    const int* __restrict__ num_clips, const int* __restrict__ num_caps)
{
    const int b = blockIdx.x;
    const int g = b >> 3;
    const bool is_im = ((b >> 2) & 1) == 0;
    const int quarter = b & 3;
    const int* __restrict__ cnt = is_im ? num_clips : num_caps;
    const float4* __restrict__ src = (const float4*)(is_im ? im : s);
    float4* __restrict__ dst = (float4*)(is_im ? g_im_mean : g_s_mean);

    const int t = threadIdx.x;

    // start = sum of counts with index < g (4 counts/thread, 2-warp reduce)
    int contrib = 0;
    #pragma unroll
    for (int u = 0; u < 4; u++) {
        int k = t + u * 64;
        int c = cnt[k];
        contrib += (k < g) ? c : 0;
    }
    #pragma unroll
    for (int o = 16; o; o >>= 1) contrib += __shfl_xor_sync(0xFFFFFFFFu, contrib, o);
    __shared__ int ws[2];
    if ((t & 31) == 0) ws[t >> 5] = contrib;
    __syncthreads();
    const int start = ws[0] + ws[1];
    const int n = cnt[g];
    const float inv = 1.0f / (float)n;

    const float4* p = src + (size_t)start * VEC4 + quarter * 64 + t;

    float ax = 0.f, ay = 0.f, az = 0.f, aw = 0.f;
    int r = 0;
    for (; r + 8 <= n; r += 8) {
        float4 x0 = p[(size_t)(r + 0) * VEC4];
        float4 x1 = p[(size_t)(r + 1) * VEC4];
        float4 x2 = p[(size_t)(r + 2) * VEC4];
        float4 x3 = p[(size_t)(r + 3) * VEC4];
        float4 x4 = p[(size_t)(r + 4) * VEC4];
        float4 x5 = p[(size_t)(r + 5) * VEC4];
        float4 x6 = p[(size_t)(r + 6) * VEC4];
        float4 x7 = p[(size_t)(r + 7) * VEC4];
        ax += (x0.x + x1.x) + (x2.x + x3.x) + ((x4.x + x5.x) + (x6.x + x7.x));
        ay += (x0.y + x1.y) + (x2.y + x3.y) + ((x4.y + x5.y) + (x6.y + x7.y));
        az += (x0.z + x1.z) + (x2.z + x3.z) + ((x4.z + x5.z) + (x6.z + x7.z));
        aw += (x0.w + x1.w) + (x2.w + x3.w) + ((x4.w + x5.w) + (x6.w + x7.w));
    }
    if (r + 4 <= n) {
        float4 x0 = p[(size_t)(r + 0) * VEC4];
        float4 x1 = p[(size_t)(r + 1) * VEC4];
        float4 x2 = p[(size_t)(r + 2) * VEC4];
        float4 x3 = p[(size_t)(r + 3) * VEC4];
        ax += (x0.x + x1.x) + (x2.x + x3.x);
        ay += (x0.y + x1.y) + (x2.y + x3.y);
        az += (x0.z + x1.z) + (x2.z + x3.z);
        aw += (x0.w + x1.w) + (x2.w + x3.w);
        r += 4;
    }
    for (; r < n; r++) {
        float4 x0 = p[(size_t)r * VEC4];
        ax += x0.x; ay += x0.y; az += x0.z; aw += x0.w;
    }

    float4 o4;
    o4.x = ax * inv; o4.y = ay * inv; o4.z = az * inv; o4.w = aw * inv;
    dst[(size_t)g * VEC4 + quarter * 64 + t] = o4;
}

// ---------------------------------------------------------------------------
// Kernel 2: K-split GEMM partials, double-buffered smem. (R7 proven)
// Grid (4,4,8), 256 threads. 64x64 tile, K=128/split in chunks of 16,
// 4x4 microtile/thread. NEW: diagonal tiles emit compact diag partials.
// ---------------------------------------------------------------------------
__global__ void __launch_bounds__(256) gemm_partial_kernel()
{
    __shared__ float As[2][16][68];
    __shared__ float Bs[2][16][68];

    const int tid = threadIdx.x;
    const int tx = tid & 15;
    const int ty = tid >> 4;
    const int bi = blockIdx.y * 64;
    const int bj = blockIdx.x * 64;
    const int kbase = blockIdx.z * (EMBED / KSPLIT);

    const int lr = tid >> 2;   // 0..63 : tile row to load
    const int lc = tid & 3;    // 0..3  : k-quad to load

    const float* Abase = &g_im_mean[(size_t)(bi + lr) * EMBED + kbase + lc * 4];
    const float* Bbase = &g_s_mean [(size_t)(bj + lr) * EMBED + kbase + lc * 4];

    float acc[4][4] = {};

    // preload chunk 0
    float4 a  = *(const float4*)Abase;
    float4 bv = *(const float4*)Bbase;
    As[0][lc * 4 + 0][lr] = a.x;  As[0][lc * 4 + 1][lr] = a.y;
    As[0][lc * 4 + 2][lr] = a.z;  As[0][lc * 4 + 3][lr] = a.w;
    Bs[0][lc * 4 + 0][lr] = bv.x; Bs[0][lc * 4 + 1][lr] = bv.y;
    Bs[0][lc * 4 + 2][lr] = bv.z; Bs[0][lc * 4 + 3][lr] = bv.w;
    __syncthreads();

    #pragma unroll
    for (int c = 0; c < 8; c++) {
        float4 an, bn;
        if (c < 7) {
            an = *(const float4*)(Abase + (c + 1) * 16);
            bn = *(const float4*)(Bbase + (c + 1) * 16);
        }
        const int cur = c & 1;
        #pragma unroll
        for (int kk = 0; kk < 16; kk++) {
            float4 av = *(const float4*)&As[cur][kk][ty * 4];
            float4 bw = *(const float4*)&Bs[cur][kk][tx * 4];
            acc[0][0] += av.x * bw.x; acc[0][1] += av.x * bw.y;
            acc[0][2] += av.x * bw.z; acc[0][3] += av.x * bw.w;
            acc[1][0] += av.y * bw.x; acc[1][1] += av.y * bw.y;
            acc[1][2] += av.y * bw.z; acc[1][3] += av.y * bw.w;
            acc[2][0] += av.z * bw.x; acc[2][1] += av.z * bw.y;
            acc[2][2] += av.z * bw.z; acc[2][3] += av.z * bw.w;
            acc[3][0] += av.w * bw.x; acc[3][1] += av.w * bw.y;
            acc[3][2] += av.w * bw.z; acc[3][3] += av.w * bw.w;
        }
        if (c < 7) {
            const int nb = (c + 1) & 1;
            As[nb][lc * 4 + 0][lr] = an.x;  As[nb][lc * 4 + 1][lr] = an.y;
            As[nb][lc * 4 + 2][lr] = an.z;  As[nb][lc * 4 + 3][lr] = an.w;
            Bs[nb][lc * 4 + 0][lr] = bn.x;  Bs[nb][lc * 4 + 1][lr] = bn.y;
            Bs[nb][lc * 4 + 2][lr] = bn.z;  Bs[nb][lc * 4 + 3][lr] = bn.w;
            __syncthreads();
        }
    }

    float* outp = g_Spart + (size_t)blockIdx.z * NPART;
    #pragma unroll
    for (int i = 0; i < 4; i++) {
        float4 v;
        v.x = acc[i][0]; v.y = acc[i][1]; v.z = acc[i][2]; v.w = acc[i][3];
        *(float4*)&outp[(size_t)(bi + ty * 4 + i) * N_GROUPS + bj + tx * 4] = v;
    }

    // compact diagonal partials (diag tiles only; element (ty*4+i, tx*4+i))
    if (blockIdx.x == blockIdx.y && tx == ty) {
        #pragma unroll
        for (int i = 0; i < 4; i++)
            g_diagpart[blockIdx.z][bi + ty * 4 + i] = acc[i][i];
    }
}

// ---------------------------------------------------------------------------
// Kernel 3: fused K-split reduce + diag + hinge loss.
// 128 blocks x 128 threads; compact diag; last-block-arrival final sum.
// ---------------------------------------------------------------------------
__global__ void __launch_bounds__(128) fused_loss_kernel(float* __restrict__ out)
{
    __shared__ float diag_s[N_GROUPS];
    __shared__ float red[4];
    __shared__ int is_last;

    const int t = threadIdx.x;
    const int b = blockIdx.x;

    #pragma unroll
    for (int u = 0; u < 2; u++) {
        const int idx = t + u * 128;
        float d = 0.f;
        #pragma unroll
        for (int z = 0; z < KSPLIT; z++)
            d += g_diagpart[z][idx];
        diag_s[idx] = d;
    }
    __syncthreads();

    const int q = b * 128 + t;          // 0..16383
    float4 v = make_float4(0.f, 0.f, 0.f, 0.f);
    #pragma unroll
    for (int z = 0; z < KSPLIT; z++) {
        float4 p = *(const float4*)&g_Spart[(size_t)z * NPART + q * 4];
        v.x += p.x; v.y += p.y; v.z += p.z; v.w += p.w;
    }

    const int i = q >> 6;
    const int j0 = (q & 63) * 4;
    const float di = diag_s[i];
    float vv[4] = {v.x, v.y, v.z, v.w};
    float sum = 0.f;
    #pragma unroll
    for (int c = 0; c < 4; c++) {
        const int j = j0 + c;
        if (j != i)
            sum += fmaxf(vv[c] - di, 0.f) + fmaxf(vv[c] - diag_s[j], 0.f);
    }

    #pragma unroll
    for (int o = 16; o; o >>= 1) sum += __shfl_xor_sync(0xFFFFFFFFu, sum, o);
    if ((t & 31) == 0) red[t >> 5] = sum;
    __syncthreads();

    if (t == 0) {
        g_loss_part[b] = red[0] + red[1] + red[2] + red[3];
        __threadfence();
        int old = atomicAdd(&g_count, 1);
        is_last = (old == LOSS_BLOCKS - 1) ? 1 : 0;
    }
    __syncthreads();

    if (is_last) {
        float v2 = __ldcg(&g_loss_part[t]);
        #pragma unroll
        for (int o = 16; o; o >>= 1) v2 += __shfl_xor_sync(0xFFFFFFFFu, v2, o);
        if ((t & 31) == 0) red[t >> 5] = v2;
        __syncthreads();
        if (t == 0) {
            out[0] = red[0] + red[1] + red[2] + red[3];
            g_count = 0;                 // reset for next replay
        }
    }
}

extern "C" void kernel_launch(void* const* d_in, const int* in_sizes, int n_in,
                              void* d_out, int out_size)
{
    const float* im        = (const float*)d_in[0];
    const float* s         = (const float*)d_in[1];
    const int*   num_clips = (const int*)d_in[2];
    const int*   num_caps  = (const int*)d_in[3];
    float* out = (float*)d_out;

    segmean_kernel<<<2048, 64>>>(im, s, num_clips, num_caps);
    gemm_partial_kernel<<<dim3(4, 4, KSPLIT), 256>>>();
    fused_loss_kernel<<<LOSS_BLOCKS, 128>>>(out);
}